// round 6
// baseline (speedup 1.0000x reference)
#include <cuda_runtime.h>
#include <math.h>

#define MAXN 32768

#define FADD __fadd_rn
#define FSUB __fsub_rn
#define FMUL __fmul_rn
#define FDIV __fdiv_rn

// 16B-aligned padded positions: one LDG.128 per neighbor gather.
__device__ float4 g_pos4[MAXN];

// ---------------------------------------------------------------------------
// Kernel A: pad pos[3*i..3*i+2] -> g_pos4[i] (w unused).
// ---------------------------------------------------------------------------
__global__ void pad_kernel(const float* __restrict__ pos, int n) {
    int i = blockIdx.x * blockDim.x + threadIdx.x;
    if (i >= n) return;
    float4 p;
    p.x = pos[3 * i + 0];
    p.y = pos[3 * i + 1];
    p.z = pos[3 * i + 2];
    p.w = 0.f;
    g_pos4[i] = p;
}

// ---------------------------------------------------------------------------
// LAPACK fp32 helpers, netlib-expression-faithful (LAPACK >= 3.10).
// FROZEN: arithmetic validated at rel_err 3.4e-7 — do not reorder.
// ---------------------------------------------------------------------------
__device__ __forceinline__ float slapy2f(float x, float y) {
    float xa = fabsf(x), ya = fabsf(y);
    float w = fmaxf(xa, ya), z = fminf(xa, ya);
    if (z == 0.f) return w;
    float t = FDIV(z, w);
    return FMUL(w, sqrtf(FADD(1.f, FMUL(t, t))));
}

__device__ __forceinline__ void slartgf(float f, float g, float& c, float& s,
                                        float& r) {
    if (g == 0.f) {
        c = 1.f; s = 0.f; r = f;
    } else if (f == 0.f) {
        c = 0.f; s = copysignf(1.f, g); r = fabsf(g);
    } else {
        float d = sqrtf(FADD(FMUL(f, f), FMUL(g, g)));
        float p = FDIV(1.f, d);
        c = FMUL(fabsf(f), p);
        s = FMUL(g, copysignf(p, f));
        r = copysignf(d, f);
    }
}

__device__ void slaev2f(float a, float b, float c0, float& rt1, float& rt2,
                        float& cs1, float& sn1) {
    float sm = FADD(a, c0);
    float df = FSUB(a, c0);
    float adf = fabsf(df);
    float tb = FADD(b, b);
    float ab = fabsf(tb);
    float acmx, acmn;
    if (fabsf(a) > fabsf(c0)) { acmx = a; acmn = c0; }
    else { acmx = c0; acmn = a; }
    float rt;
    if (adf > ab) {
        float t = FDIV(ab, adf);
        rt = FMUL(adf, sqrtf(FADD(1.f, FMUL(t, t))));
    } else if (adf < ab) {
        float t = FDIV(adf, ab);
        rt = FMUL(ab, sqrtf(FADD(1.f, FMUL(t, t))));
    } else {
        rt = FMUL(ab, sqrtf(2.f));
    }
    int sgn1;
    if (sm < 0.f) {
        rt1 = FMUL(0.5f, FSUB(sm, rt)); sgn1 = -1;
        rt2 = FSUB(FMUL(FDIV(acmx, rt1), acmn), FMUL(FDIV(b, rt1), b));
    } else if (sm > 0.f) {
        rt1 = FMUL(0.5f, FADD(sm, rt)); sgn1 = 1;
        rt2 = FSUB(FMUL(FDIV(acmx, rt1), acmn), FMUL(FDIV(b, rt1), b));
    } else {
        rt1 = FMUL(0.5f, rt); rt2 = FMUL(-0.5f, rt); sgn1 = 1;
    }
    int sgn2;
    float cs;
    if (df >= 0.f) { cs = FADD(df, rt); sgn2 = 1; }
    else { cs = FSUB(df, rt); sgn2 = -1; }
    float acs = fabsf(cs);
    if (acs > ab) {
        float ct = FDIV(-tb, cs);
        sn1 = FDIV(1.f, sqrtf(FADD(1.f, FMUL(ct, ct))));
        cs1 = FMUL(ct, sn1);
    } else {
        if (ab == 0.f) { cs1 = 1.f; sn1 = 0.f; }
        else {
            float tn = FDIV(-cs, tb);
            cs1 = FDIV(1.f, sqrtf(FADD(1.f, FMUL(tn, tn))));
            sn1 = FMUL(tn, cs1);
        }
    }
    if (sgn1 == sgn2) { float tau = cs1; cs1 = -sn1; sn1 = tau; }
}

// Covariance accumulation step (frozen sequential order).
__device__ __forceinline__ void cov_acc(float4 q, float px, float py, float pz,
                                        float& a00, float& a10, float& a20,
                                        float& a11, float& a21, float& a22) {
    float dx = FSUB(q.x, px);
    float dy = FSUB(q.y, py);
    float dz = FSUB(q.z, pz);
    a00 = FADD(a00, FMUL(dx, dx));
    a10 = FADD(a10, FMUL(dx, dy));
    a20 = FADD(a20, FMUL(dx, dz));
    a11 = FADD(a11, FMUL(dy, dy));
    a21 = FADD(a21, FMUL(dy, dz));
    a22 = FADD(a22, FMUL(dz, dz));
}

// ---------------------------------------------------------------------------
// Kernel B (fused): thread-per-node covariance -> LAPACK ssyevd replica.
// ---------------------------------------------------------------------------
__global__ void __launch_bounds__(128)
fused_kernel(const int* __restrict__ edge_src,
             const int* __restrict__ num_neighbors,
             float* __restrict__ out, int n, int k) {
    int gi = blockIdx.x * blockDim.x + threadIdx.x;
    if (gi >= n) return;
    float* o = out + (long long)gi * 9;
    if (num_neighbors[gi] <= 1) {
#pragma unroll
        for (int j = 0; j < 9; j++) o[j] = 0.f;
        return;
    }

    // ================= covariance (frozen arithmetic order) ==============
    float4 pc = g_pos4[gi];
    float px = pc.x, py = pc.y, pz = pc.z;
    float a00 = 0.f, a10 = 0.f, a20 = 0.f, a11 = 0.f, a21 = 0.f, a22 = 0.f;
    const int4* es4 = (const int4*)(edge_src + (long long)gi * k);

    if (k == 64) {
        // Specialized full-unroll path: maximize outstanding LDGs (occupancy
        // is grid-limited, so register pressure is free).
        int4 idx[16];
#pragma unroll
        for (int j = 0; j < 16; j++) idx[j] = es4[j];
#pragma unroll
        for (int j = 0; j < 16; j++) {
            float4 q0 = __ldg(&g_pos4[idx[j].x]);
            float4 q1 = __ldg(&g_pos4[idx[j].y]);
            float4 q2 = __ldg(&g_pos4[idx[j].z]);
            float4 q3 = __ldg(&g_pos4[idx[j].w]);
            cov_acc(q0, px, py, pz, a00, a10, a20, a11, a21, a22);
            cov_acc(q1, px, py, pz, a00, a10, a20, a11, a21, a22);
            cov_acc(q2, px, py, pz, a00, a10, a20, a11, a21, a22);
            cov_acc(q3, px, py, pz, a00, a10, a20, a11, a21, a22);
        }
    } else {
        for (int j = 0; j < k / 4; j++) {
            int4 s4 = es4[j];
            float4 q0 = __ldg(&g_pos4[s4.x]);
            float4 q1 = __ldg(&g_pos4[s4.y]);
            float4 q2 = __ldg(&g_pos4[s4.z]);
            float4 q3 = __ldg(&g_pos4[s4.w]);
            cov_acc(q0, px, py, pz, a00, a10, a20, a11, a21, a22);
            cov_acc(q1, px, py, pz, a00, a10, a20, a11, a21, a22);
            cov_acc(q2, px, py, pz, a00, a10, a20, a11, a21, a22);
            cov_acc(q3, px, py, pz, a00, a10, a20, a11, a21, a22);
        }
    }

    // ================= SSYTD2 (lower), n=3 =================
    float d[4], e[3];
    float tau1 = 0.f, v3 = 0.f;
    {
        float alpha = a10;   // A(2,1)
        float x = a20;       // A(3,1)
        if (x == 0.f) {
            tau1 = 0.f;
            e[1] = alpha;
        } else {
            float beta = -copysignf(slapy2f(alpha, x), alpha);
            tau1 = FDIV(FSUB(beta, alpha), beta);
            float rcp = FDIV(1.f, FSUB(alpha, beta));
            v3 = FMUL(x, rcp);
            e[1] = beta;
            float w1 = FADD(FMUL(tau1, a11), FMUL(tau1, FMUL(a21, v3)));
            float w2 = FADD(FMUL(tau1, a21), FMUL(FMUL(tau1, v3), a22));
            float dot = FADD(w1, FMUL(w2, v3));
            float al2 = -FMUL(FMUL(0.5f, tau1), dot);
            w1 = FADD(w1, al2);
            w2 = FADD(w2, FMUL(al2, v3));
            a11 = FADD(FADD(a11, -w1), -w1);
            a21 = FADD(FADD(a21, FMUL(v3, -w1)), -w2);
            a22 = FADD(FADD(a22, FMUL(v3, -w2)), FMUL(w2, -v3));
        }
        e[2] = a21;
        d[1] = a00; d[2] = a11; d[3] = a22;
    }

    // ================= SSTEQR('I'), n=3 =================
    const float eps = 5.9604644775390625e-08f;
    const float eps2 = FMUL(eps, eps);
    const float safmin = 1.1754943508222875e-38f;
    const int nn = 3;
    const int nmaxit = nn * 30;
    int jtot = 0;

    float Z[4][4];
#pragma unroll
    for (int i = 1; i <= 3; i++)
#pragma unroll
        for (int j = 1; j <= 3; j++) Z[i][j] = (i == j) ? 1.f : 0.f;

    float wc[3], ws[3];

    int l1 = 1;
    while (l1 <= nn) {
        if (l1 > 1) e[l1 - 1] = 0.f;
        int m = nn;
        for (int mm = l1; mm <= nn - 1; mm++) {
            float tst = fabsf(e[mm]);
            if (tst == 0.f) { m = mm; break; }
            if (tst <= FMUL(FMUL(sqrtf(fabsf(d[mm])), sqrtf(fabsf(d[mm + 1]))),
                            eps)) {
                e[mm] = 0.f; m = mm; break;
            }
        }
        int l = l1, lsv = l, lend = m, lendsv = lend;
        l1 = m + 1;
        if (lend == l) continue;

        float anorm = 0.f;
        for (int i = l; i <= lend; i++) anorm = fmaxf(anorm, fabsf(d[i]));
        for (int i = l; i <= lend - 1; i++) anorm = fmaxf(anorm, fabsf(e[i]));
        if (anorm == 0.f) continue;

        if (fabsf(d[lend]) < fabsf(d[l])) { lend = lsv; l = lendsv; }

        if (lend > l) {
            // ---------------- QL iteration ----------------
            while (1) {
                int m2 = lend;
                if (l != lend) {
                    for (int mm = l; mm <= lend - 1; mm++) {
                        float tst = FMUL(e[mm], e[mm]);
                        if (tst <= FADD(FMUL(FMUL(eps2, fabsf(d[mm])),
                                             fabsf(d[mm + 1])), safmin)) {
                            m2 = mm; break;
                        }
                    }
                }
                if (m2 < lend) e[m2] = 0.f;
                float p = d[l];
                if (m2 == l) {
                    d[l] = p;
                    l = l + 1;
                    if (l <= lend) continue;
                    break;
                }
                if (m2 == l + 1) {
                    float rt1, rt2, c, s;
                    slaev2f(d[l], e[l], d[l + 1], rt1, rt2, c, s);
#pragma unroll
                    for (int i = 1; i <= nn; i++) {
                        float temp = Z[i][l + 1];
                        Z[i][l + 1] = FSUB(FMUL(c, temp), FMUL(s, Z[i][l]));
                        Z[i][l] = FADD(FMUL(s, temp), FMUL(c, Z[i][l]));
                    }
                    d[l] = rt1; d[l + 1] = rt2; e[l] = 0.f;
                    l = l + 2;
                    if (l <= lend) continue;
                    break;
                }
                if (jtot == nmaxit) break;
                jtot++;
                float g = FDIV(FSUB(d[l + 1], p), FMUL(2.f, e[l]));
                float r = slapy2f(g, 1.f);
                g = FADD(FSUB(d[m2], p),
                         FDIV(e[l], FADD(g, copysignf(r, g))));
                float s = 1.f, c = 1.f;
                p = 0.f;
                for (int i = m2 - 1; i >= l; i--) {
                    float f = FMUL(s, e[i]);
                    float b = FMUL(c, e[i]);
                    slartgf(g, f, c, s, r);
                    if (i != m2 - 1) e[i + 1] = r;
                    g = FSUB(d[i + 1], p);
                    r = FADD(FMUL(FSUB(d[i], g), s), FMUL(FMUL(2.f, c), b));
                    p = FMUL(s, r);
                    d[i + 1] = FADD(g, p);
                    g = FSUB(FMUL(c, r), b);
                    wc[i] = c;
                    ws[i] = -s;
                }
                for (int j = m2 - l; j >= 1; j--) {
                    float cj = wc[l + j - 1], sj = ws[l + j - 1];
                    if (cj != 1.f || sj != 0.f) {
#pragma unroll
                        for (int i = 1; i <= nn; i++) {
                            float temp = Z[i][l + j];
                            Z[i][l + j] =
                                FSUB(FMUL(cj, temp), FMUL(sj, Z[i][l + j - 1]));
                            Z[i][l + j - 1] =
                                FADD(FMUL(sj, temp), FMUL(cj, Z[i][l + j - 1]));
                        }
                    }
                }
                d[l] = FSUB(d[l], p);
                e[l] = g;
            }
        } else {
            // ---------------- QR iteration ----------------
            while (1) {
                int m2 = lend;
                if (l != lend) {
                    for (int mm = l; mm >= lend + 1; mm--) {
                        float tst = FMUL(e[mm - 1], e[mm - 1]);
                        if (tst <= FADD(FMUL(FMUL(eps2, fabsf(d[mm])),
                                             fabsf(d[mm - 1])), safmin)) {
                            m2 = mm; break;
                        }
                    }
                }
                if (m2 > lend) e[m2 - 1] = 0.f;
                float p = d[l];
                if (m2 == l) {
                    d[l] = p;
                    l = l - 1;
                    if (l >= lend) continue;
                    break;
                }
                if (m2 == l - 1) {
                    float rt1, rt2, c, s;
                    slaev2f(d[l - 1], e[l - 1], d[l], rt1, rt2, c, s);
#pragma unroll
                    for (int i = 1; i <= nn; i++) {
                        float temp = Z[i][l];
                        Z[i][l] = FSUB(FMUL(c, temp), FMUL(s, Z[i][l - 1]));
                        Z[i][l - 1] = FADD(FMUL(s, temp), FMUL(c, Z[i][l - 1]));
                    }
                    d[l - 1] = rt1; d[l] = rt2; e[l - 1] = 0.f;
                    l = l - 2;
                    if (l >= lend) continue;
                    break;
                }
                if (jtot == nmaxit) break;
                jtot++;
                float g = FDIV(FSUB(d[l - 1], p), FMUL(2.f, e[l - 1]));
                float r = slapy2f(g, 1.f);
                g = FADD(FSUB(d[m2], p),
                         FDIV(e[l - 1], FADD(g, copysignf(r, g))));
                float s = 1.f, c = 1.f;
                p = 0.f;
                for (int i = m2; i <= l - 1; i++) {
                    float f = FMUL(s, e[i]);
                    float b = FMUL(c, e[i]);
                    slartgf(g, f, c, s, r);
                    if (i != m2) e[i - 1] = r;
                    g = FSUB(d[i], p);
                    r = FADD(FMUL(FSUB(d[i + 1], g), s), FMUL(FMUL(2.f, c), b));
                    p = FMUL(s, r);
                    d[i] = FADD(g, p);
                    g = FSUB(FMUL(c, r), b);
                    wc[i] = c;
                    ws[i] = s;
                }
                for (int j = 1; j <= l - m2; j++) {
                    float cj = wc[m2 + j - 1], sj = ws[m2 + j - 1];
                    if (cj != 1.f || sj != 0.f) {
#pragma unroll
                        for (int i = 1; i <= nn; i++) {
                            float temp = Z[i][m2 + j];
                            Z[i][m2 + j] =
                                FSUB(FMUL(cj, temp), FMUL(sj, Z[i][m2 + j - 1]));
                            Z[i][m2 + j - 1] =
                                FADD(FMUL(sj, temp), FMUL(cj, Z[i][m2 + j - 1]));
                        }
                    }
                }
                d[l] = FSUB(d[l], p);
                e[l - 1] = g;
            }
        }
    }

    // ssteqr final selection sort (ascending, column swaps)
    for (int ii = 2; ii <= nn; ii++) {
        int i = ii - 1;
        int kk = i;
        float p = d[i];
        for (int j = ii; j <= nn; j++) {
            if (d[j] < p) { kk = j; p = d[j]; }
        }
        if (kk != i) {
            d[kk] = d[i];
            d[i] = p;
#pragma unroll
            for (int row = 1; row <= nn; row++) {
                float t = Z[row][i];
                Z[row][i] = Z[row][kk];
                Z[row][kk] = t;
            }
        }
    }

    // ================= SORMTR ('L','L','N'): Z := H(1)*Z =================
    if (tau1 != 0.f) {
#pragma unroll
        for (int j = 1; j <= 3; j++) {
            float w = FADD(Z[2][j], FMUL(Z[3][j], v3));
            float t = FMUL(-tau1, w);
            Z[2][j] = FADD(Z[2][j], t);
            Z[3][j] = FADD(Z[3][j], FMUL(v3, t));
        }
    }

    // frames[a][b] = vecs[b][a]  =>  out[3a+b] = Z[b+1][a+1]
    o[0] = Z[1][1]; o[1] = Z[2][1]; o[2] = Z[3][1];
    o[3] = Z[1][2]; o[4] = Z[2][2]; o[5] = Z[3][2];
    o[6] = Z[1][3]; o[7] = Z[2][3]; o[8] = Z[3][3];
}

// ---------------------------------------------------------------------------
// Launch
// ---------------------------------------------------------------------------
extern "C" void kernel_launch(void* const* d_in, const int* in_sizes, int n_in,
                              void* d_out, int out_size) {
    const float* pos = (const float*)d_in[0];
    const int* edge_src = (const int*)d_in[1];
    // d_in[2] = edge_dst: unused (edge_dst == repeat(arange(n), k))
    const int* num_neighbors = (const int*)d_in[3];

    int n = in_sizes[3];
    int k = in_sizes[1] / n;

    pad_kernel<<<(n + 255) / 256, 256>>>(pos, n);
    fused_kernel<<<(n + 127) / 128, 128>>>(edge_src, num_neighbors,
                                           (float*)d_out, n, k);
}

// round 7
// speedup vs baseline: 1.1674x; 1.1674x over previous
#include <cuda_runtime.h>
#include <math.h>

#define MAXN 32768

#define FADD __fadd_rn
#define FSUB __fsub_rn
#define FMUL __fmul_rn
#define FDIV __fdiv_rn

// 16B-aligned padded positions: one LDG.128 per neighbor gather.
__device__ float4 g_pos4[MAXN];

// ---------------------------------------------------------------------------
// Kernel A: pad pos[3*i..3*i+2] -> g_pos4[i] (w unused).
// ---------------------------------------------------------------------------
__global__ void pad_kernel(const float* __restrict__ pos, int n) {
    int i = blockIdx.x * blockDim.x + threadIdx.x;
    if (i >= n) return;
    float4 p;
    p.x = pos[3 * i + 0];
    p.y = pos[3 * i + 1];
    p.z = pos[3 * i + 2];
    p.w = 0.f;
    g_pos4[i] = p;
}

// ---------------------------------------------------------------------------
// LAPACK fp32 helpers, netlib-expression-faithful (LAPACK >= 3.10).
// FROZEN: arithmetic validated at rel_err 3.4e-7 — do not reorder.
// ---------------------------------------------------------------------------
__device__ __forceinline__ float slapy2f(float x, float y) {
    float xa = fabsf(x), ya = fabsf(y);
    float w = fmaxf(xa, ya), z = fminf(xa, ya);
    if (z == 0.f) return w;
    float t = FDIV(z, w);
    return FMUL(w, sqrtf(FADD(1.f, FMUL(t, t))));
}

__device__ __forceinline__ void slartgf(float f, float g, float& c, float& s,
                                        float& r) {
    if (g == 0.f) {
        c = 1.f; s = 0.f; r = f;
    } else if (f == 0.f) {
        c = 0.f; s = copysignf(1.f, g); r = fabsf(g);
    } else {
        float d = sqrtf(FADD(FMUL(f, f), FMUL(g, g)));
        float p = FDIV(1.f, d);
        c = FMUL(fabsf(f), p);
        s = FMUL(g, copysignf(p, f));
        r = copysignf(d, f);
    }
}

__device__ void slaev2f(float a, float b, float c0, float& rt1, float& rt2,
                        float& cs1, float& sn1) {
    float sm = FADD(a, c0);
    float df = FSUB(a, c0);
    float adf = fabsf(df);
    float tb = FADD(b, b);
    float ab = fabsf(tb);
    float acmx, acmn;
    if (fabsf(a) > fabsf(c0)) { acmx = a; acmn = c0; }
    else { acmx = c0; acmn = a; }
    float rt;
    if (adf > ab) {
        float t = FDIV(ab, adf);
        rt = FMUL(adf, sqrtf(FADD(1.f, FMUL(t, t))));
    } else if (adf < ab) {
        float t = FDIV(adf, ab);
        rt = FMUL(ab, sqrtf(FADD(1.f, FMUL(t, t))));
    } else {
        rt = FMUL(ab, sqrtf(2.f));
    }
    int sgn1;
    if (sm < 0.f) {
        rt1 = FMUL(0.5f, FSUB(sm, rt)); sgn1 = -1;
        rt2 = FSUB(FMUL(FDIV(acmx, rt1), acmn), FMUL(FDIV(b, rt1), b));
    } else if (sm > 0.f) {
        rt1 = FMUL(0.5f, FADD(sm, rt)); sgn1 = 1;
        rt2 = FSUB(FMUL(FDIV(acmx, rt1), acmn), FMUL(FDIV(b, rt1), b));
    } else {
        rt1 = FMUL(0.5f, rt); rt2 = FMUL(-0.5f, rt); sgn1 = 1;
    }
    int sgn2;
    float cs;
    if (df >= 0.f) { cs = FADD(df, rt); sgn2 = 1; }
    else { cs = FSUB(df, rt); sgn2 = -1; }
    float acs = fabsf(cs);
    if (acs > ab) {
        float ct = FDIV(-tb, cs);
        sn1 = FDIV(1.f, sqrtf(FADD(1.f, FMUL(ct, ct))));
        cs1 = FMUL(ct, sn1);
    } else {
        if (ab == 0.f) { cs1 = 1.f; sn1 = 0.f; }
        else {
            float tn = FDIV(-cs, tb);
            cs1 = FDIV(1.f, sqrtf(FADD(1.f, FMUL(tn, tn))));
            sn1 = FMUL(tn, cs1);
        }
    }
    if (sgn1 == sgn2) { float tau = cs1; cs1 = -sn1; sn1 = tau; }
}

// Covariance accumulation step (frozen sequential order).
__device__ __forceinline__ void cov_acc(float4 q, float px, float py, float pz,
                                        float& a00, float& a10, float& a20,
                                        float& a11, float& a21, float& a22) {
    float dx = FSUB(q.x, px);
    float dy = FSUB(q.y, py);
    float dz = FSUB(q.z, pz);
    a00 = FADD(a00, FMUL(dx, dx));
    a10 = FADD(a10, FMUL(dx, dy));
    a20 = FADD(a20, FMUL(dx, dz));
    a11 = FADD(a11, FMUL(dy, dy));
    a21 = FADD(a21, FMUL(dy, dz));
    a22 = FADD(a22, FMUL(dz, dz));
}

// ---------------------------------------------------------------------------
// Kernel B (fused): thread-per-node covariance -> LAPACK ssyevd replica.
// __launch_bounds__(128, 1): occupancy is grid-limited (1024 warps chip-wide)
// so grant ptxas the full register budget — prevents local-mem demotion.
// ---------------------------------------------------------------------------
__global__ void __launch_bounds__(128, 1)
fused_kernel(const int* __restrict__ edge_src,
             const int* __restrict__ num_neighbors,
             float* __restrict__ out, int n, int k) {
    int gi = blockIdx.x * blockDim.x + threadIdx.x;
    if (gi >= n) return;
    float* o = out + (long long)gi * 9;
    if (num_neighbors[gi] <= 1) {
#pragma unroll
        for (int j = 0; j < 9; j++) o[j] = 0.f;
        return;
    }

    // ================= covariance (frozen arithmetic order) ==============
    float4 pc = g_pos4[gi];
    float px = pc.x, py = pc.y, pz = pc.z;
    float a00 = 0.f, a10 = 0.f, a20 = 0.f, a11 = 0.f, a21 = 0.f, a22 = 0.f;
    const int4* es4 = (const int4*)(edge_src + (long long)gi * k);
#pragma unroll 4
    for (int j = 0; j < k / 4; j++) {
        int4 s4 = es4[j];
        float4 q0 = __ldg(&g_pos4[s4.x]);
        float4 q1 = __ldg(&g_pos4[s4.y]);
        float4 q2 = __ldg(&g_pos4[s4.z]);
        float4 q3 = __ldg(&g_pos4[s4.w]);
        cov_acc(q0, px, py, pz, a00, a10, a20, a11, a21, a22);
        cov_acc(q1, px, py, pz, a00, a10, a20, a11, a21, a22);
        cov_acc(q2, px, py, pz, a00, a10, a20, a11, a21, a22);
        cov_acc(q3, px, py, pz, a00, a10, a20, a11, a21, a22);
    }

    // ================= SSYTD2 (lower), n=3 =================
    float d[4], e[3];
    float tau1 = 0.f, v3 = 0.f;
    {
        float alpha = a10;   // A(2,1)
        float x = a20;       // A(3,1)
        if (x == 0.f) {
            tau1 = 0.f;
            e[1] = alpha;
        } else {
            float beta = -copysignf(slapy2f(alpha, x), alpha);
            tau1 = FDIV(FSUB(beta, alpha), beta);
            float rcp = FDIV(1.f, FSUB(alpha, beta));
            v3 = FMUL(x, rcp);
            e[1] = beta;
            float w1 = FADD(FMUL(tau1, a11), FMUL(tau1, FMUL(a21, v3)));
            float w2 = FADD(FMUL(tau1, a21), FMUL(FMUL(tau1, v3), a22));
            float dot = FADD(w1, FMUL(w2, v3));
            float al2 = -FMUL(FMUL(0.5f, tau1), dot);
            w1 = FADD(w1, al2);
            w2 = FADD(w2, FMUL(al2, v3));
            a11 = FADD(FADD(a11, -w1), -w1);
            a21 = FADD(FADD(a21, FMUL(v3, -w1)), -w2);
            a22 = FADD(FADD(a22, FMUL(v3, -w2)), FMUL(w2, -v3));
        }
        e[2] = a21;
        d[1] = a00; d[2] = a11; d[3] = a22;
    }

    // ================= SSTEQR('I'), n=3 =================
    const float eps = 5.9604644775390625e-08f;
    const float eps2 = FMUL(eps, eps);
    const float safmin = 1.1754943508222875e-38f;
    const int nn = 3;
    const int nmaxit = nn * 30;
    int jtot = 0;

    float Z[4][4];
#pragma unroll
    for (int i = 1; i <= 3; i++)
#pragma unroll
        for (int j = 1; j <= 3; j++) Z[i][j] = (i == j) ? 1.f : 0.f;

    float wc[3], ws[3];

    int l1 = 1;
    while (l1 <= nn) {
        if (l1 > 1) e[l1 - 1] = 0.f;
        int m = nn;
        for (int mm = l1; mm <= nn - 1; mm++) {
            float tst = fabsf(e[mm]);
            if (tst == 0.f) { m = mm; break; }
            if (tst <= FMUL(FMUL(sqrtf(fabsf(d[mm])), sqrtf(fabsf(d[mm + 1]))),
                            eps)) {
                e[mm] = 0.f; m = mm; break;
            }
        }
        int l = l1, lsv = l, lend = m, lendsv = lend;
        l1 = m + 1;
        if (lend == l) continue;

        float anorm = 0.f;
        for (int i = l; i <= lend; i++) anorm = fmaxf(anorm, fabsf(d[i]));
        for (int i = l; i <= lend - 1; i++) anorm = fmaxf(anorm, fabsf(e[i]));
        if (anorm == 0.f) continue;

        if (fabsf(d[lend]) < fabsf(d[l])) { lend = lsv; l = lendsv; }

        if (lend > l) {
            // ---------------- QL iteration ----------------
            while (1) {
                int m2 = lend;
                if (l != lend) {
                    for (int mm = l; mm <= lend - 1; mm++) {
                        float tst = FMUL(e[mm], e[mm]);
                        if (tst <= FADD(FMUL(FMUL(eps2, fabsf(d[mm])),
                                             fabsf(d[mm + 1])), safmin)) {
                            m2 = mm; break;
                        }
                    }
                }
                if (m2 < lend) e[m2] = 0.f;
                float p = d[l];
                if (m2 == l) {
                    d[l] = p;
                    l = l + 1;
                    if (l <= lend) continue;
                    break;
                }
                if (m2 == l + 1) {
                    float rt1, rt2, c, s;
                    slaev2f(d[l], e[l], d[l + 1], rt1, rt2, c, s);
#pragma unroll
                    for (int i = 1; i <= nn; i++) {
                        float temp = Z[i][l + 1];
                        Z[i][l + 1] = FSUB(FMUL(c, temp), FMUL(s, Z[i][l]));
                        Z[i][l] = FADD(FMUL(s, temp), FMUL(c, Z[i][l]));
                    }
                    d[l] = rt1; d[l + 1] = rt2; e[l] = 0.f;
                    l = l + 2;
                    if (l <= lend) continue;
                    break;
                }
                if (jtot == nmaxit) break;
                jtot++;
                float g = FDIV(FSUB(d[l + 1], p), FMUL(2.f, e[l]));
                float r = slapy2f(g, 1.f);
                g = FADD(FSUB(d[m2], p),
                         FDIV(e[l], FADD(g, copysignf(r, g))));
                float s = 1.f, c = 1.f;
                p = 0.f;
                for (int i = m2 - 1; i >= l; i--) {
                    float f = FMUL(s, e[i]);
                    float b = FMUL(c, e[i]);
                    slartgf(g, f, c, s, r);
                    if (i != m2 - 1) e[i + 1] = r;
                    g = FSUB(d[i + 1], p);
                    r = FADD(FMUL(FSUB(d[i], g), s), FMUL(FMUL(2.f, c), b));
                    p = FMUL(s, r);
                    d[i + 1] = FADD(g, p);
                    g = FSUB(FMUL(c, r), b);
                    wc[i] = c;
                    ws[i] = -s;
                }
                for (int j = m2 - l; j >= 1; j--) {
                    float cj = wc[l + j - 1], sj = ws[l + j - 1];
                    if (cj != 1.f || sj != 0.f) {
#pragma unroll
                        for (int i = 1; i <= nn; i++) {
                            float temp = Z[i][l + j];
                            Z[i][l + j] =
                                FSUB(FMUL(cj, temp), FMUL(sj, Z[i][l + j - 1]));
                            Z[i][l + j - 1] =
                                FADD(FMUL(sj, temp), FMUL(cj, Z[i][l + j - 1]));
                        }
                    }
                }
                d[l] = FSUB(d[l], p);
                e[l] = g;
            }
        } else {
            // ---------------- QR iteration ----------------
            while (1) {
                int m2 = lend;
                if (l != lend) {
                    for (int mm = l; mm >= lend + 1; mm--) {
                        float tst = FMUL(e[mm - 1], e[mm - 1]);
                        if (tst <= FADD(FMUL(FMUL(eps2, fabsf(d[mm])),
                                             fabsf(d[mm - 1])), safmin)) {
                            m2 = mm; break;
                        }
                    }
                }
                if (m2 > lend) e[m2 - 1] = 0.f;
                float p = d[l];
                if (m2 == l) {
                    d[l] = p;
                    l = l - 1;
                    if (l >= lend) continue;
                    break;
                }
                if (m2 == l - 1) {
                    float rt1, rt2, c, s;
                    slaev2f(d[l - 1], e[l - 1], d[l], rt1, rt2, c, s);
#pragma unroll
                    for (int i = 1; i <= nn; i++) {
                        float temp = Z[i][l];
                        Z[i][l] = FSUB(FMUL(c, temp), FMUL(s, Z[i][l - 1]));
                        Z[i][l - 1] = FADD(FMUL(s, temp), FMUL(c, Z[i][l - 1]));
                    }
                    d[l - 1] = rt1; d[l] = rt2; e[l - 1] = 0.f;
                    l = l - 2;
                    if (l >= lend) continue;
                    break;
                }
                if (jtot == nmaxit) break;
                jtot++;
                float g = FDIV(FSUB(d[l - 1], p), FMUL(2.f, e[l - 1]));
                float r = slapy2f(g, 1.f);
                g = FADD(FSUB(d[m2], p),
                         FDIV(e[l - 1], FADD(g, copysignf(r, g))));
                float s = 1.f, c = 1.f;
                p = 0.f;
                for (int i = m2; i <= l - 1; i++) {
                    float f = FMUL(s, e[i]);
                    float b = FMUL(c, e[i]);
                    slartgf(g, f, c, s, r);
                    if (i != m2) e[i - 1] = r;
                    g = FSUB(d[i], p);
                    r = FADD(FMUL(FSUB(d[i + 1], g), s), FMUL(FMUL(2.f, c), b));
                    p = FMUL(s, r);
                    d[i] = FADD(g, p);
                    g = FSUB(FMUL(c, r), b);
                    wc[i] = c;
                    ws[i] = s;
                }
                for (int j = 1; j <= l - m2; j++) {
                    float cj = wc[m2 + j - 1], sj = ws[m2 + j - 1];
                    if (cj != 1.f || sj != 0.f) {
#pragma unroll
                        for (int i = 1; i <= nn; i++) {
                            float temp = Z[i][m2 + j];
                            Z[i][m2 + j] =
                                FSUB(FMUL(cj, temp), FMUL(sj, Z[i][m2 + j - 1]));
                            Z[i][m2 + j - 1] =
                                FADD(FMUL(sj, temp), FMUL(cj, Z[i][m2 + j - 1]));
                        }
                    }
                }
                d[l] = FSUB(d[l], p);
                e[l - 1] = g;
            }
        }
    }

    // ssteqr final selection sort (ascending, column swaps)
    for (int ii = 2; ii <= nn; ii++) {
        int i = ii - 1;
        int kk = i;
        float p = d[i];
        for (int j = ii; j <= nn; j++) {
            if (d[j] < p) { kk = j; p = d[j]; }
        }
        if (kk != i) {
            d[kk] = d[i];
            d[i] = p;
#pragma unroll
            for (int row = 1; row <= nn; row++) {
                float t = Z[row][i];
                Z[row][i] = Z[row][kk];
                Z[row][kk] = t;
            }
        }
    }

    // ================= SORMTR ('L','L','N'): Z := H(1)*Z =================
    if (tau1 != 0.f) {
#pragma unroll
        for (int j = 1; j <= 3; j++) {
            float w = FADD(Z[2][j], FMUL(Z[3][j], v3));
            float t = FMUL(-tau1, w);
            Z[2][j] = FADD(Z[2][j], t);
            Z[3][j] = FADD(Z[3][j], FMUL(v3, t));
        }
    }

    // frames[a][b] = vecs[b][a]  =>  out[3a+b] = Z[b+1][a+1]
    o[0] = Z[1][1]; o[1] = Z[2][1]; o[2] = Z[3][1];
    o[3] = Z[1][2]; o[4] = Z[2][2]; o[5] = Z[3][2];
    o[6] = Z[1][3]; o[7] = Z[2][3]; o[8] = Z[3][3];
}

// ---------------------------------------------------------------------------
// Launch
// ---------------------------------------------------------------------------
extern "C" void kernel_launch(void* const* d_in, const int* in_sizes, int n_in,
                              void* d_out, int out_size) {
    const float* pos = (const float*)d_in[0];
    const int* edge_src = (const int*)d_in[1];
    // d_in[2] = edge_dst: unused (edge_dst == repeat(arange(n), k))
    const int* num_neighbors = (const int*)d_in[3];

    int n = in_sizes[3];
    int k = in_sizes[1] / n;

    pad_kernel<<<(n + 255) / 256, 256>>>(pos, n);
    fused_kernel<<<(n + 127) / 128, 128>>>(edge_src, num_neighbors,
                                           (float*)d_out, n, k);
}

// round 8
// speedup vs baseline: 1.3066x; 1.1192x over previous
#include <cuda_runtime.h>
#include <math.h>

#define MAXN 32768

#define FADD __fadd_rn
#define FSUB __fsub_rn
#define FMUL __fmul_rn
#define FDIV __fdiv_rn

// 16B-aligned padded positions: one LDG.128 per neighbor gather.
__device__ float4 g_pos4[MAXN];

// ---------------------------------------------------------------------------
// Kernel A: pad pos[3*i..3*i+2] -> g_pos4[i] (w unused).
// ---------------------------------------------------------------------------
__global__ void pad_kernel(const float* __restrict__ pos, int n) {
    int i = blockIdx.x * blockDim.x + threadIdx.x;
    if (i >= n) return;
    float4 p;
    p.x = pos[3 * i + 0];
    p.y = pos[3 * i + 1];
    p.z = pos[3 * i + 2];
    p.w = 0.f;
    g_pos4[i] = p;
}

// ---------------------------------------------------------------------------
// LAPACK fp32 helpers, netlib-expression-faithful (LAPACK >= 3.10).
// FROZEN: arithmetic validated at rel_err 3.4e-7 — do not reorder.
// ---------------------------------------------------------------------------
__device__ __forceinline__ float slapy2f(float x, float y) {
    float xa = fabsf(x), ya = fabsf(y);
    float w = fmaxf(xa, ya), z = fminf(xa, ya);
    if (z == 0.f) return w;
    float t = FDIV(z, w);
    return FMUL(w, sqrtf(FADD(1.f, FMUL(t, t))));
}

__device__ __forceinline__ void slartgf(float f, float g, float& c, float& s,
                                        float& r) {
    if (g == 0.f) {
        c = 1.f; s = 0.f; r = f;
    } else if (f == 0.f) {
        c = 0.f; s = copysignf(1.f, g); r = fabsf(g);
    } else {
        float d = sqrtf(FADD(FMUL(f, f), FMUL(g, g)));
        float p = FDIV(1.f, d);
        c = FMUL(fabsf(f), p);
        s = FMUL(g, copysignf(p, f));
        r = copysignf(d, f);
    }
}

__device__ void slaev2f(float a, float b, float c0, float& rt1, float& rt2,
                        float& cs1, float& sn1) {
    float sm = FADD(a, c0);
    float df = FSUB(a, c0);
    float adf = fabsf(df);
    float tb = FADD(b, b);
    float ab = fabsf(tb);
    float acmx, acmn;
    if (fabsf(a) > fabsf(c0)) { acmx = a; acmn = c0; }
    else { acmx = c0; acmn = a; }
    float rt;
    if (adf > ab) {
        float t = FDIV(ab, adf);
        rt = FMUL(adf, sqrtf(FADD(1.f, FMUL(t, t))));
    } else if (adf < ab) {
        float t = FDIV(adf, ab);
        rt = FMUL(ab, sqrtf(FADD(1.f, FMUL(t, t))));
    } else {
        rt = FMUL(ab, sqrtf(2.f));
    }
    int sgn1;
    if (sm < 0.f) {
        rt1 = FMUL(0.5f, FSUB(sm, rt)); sgn1 = -1;
        rt2 = FSUB(FMUL(FDIV(acmx, rt1), acmn), FMUL(FDIV(b, rt1), b));
    } else if (sm > 0.f) {
        rt1 = FMUL(0.5f, FADD(sm, rt)); sgn1 = 1;
        rt2 = FSUB(FMUL(FDIV(acmx, rt1), acmn), FMUL(FDIV(b, rt1), b));
    } else {
        rt1 = FMUL(0.5f, rt); rt2 = FMUL(-0.5f, rt); sgn1 = 1;
    }
    int sgn2;
    float cs;
    if (df >= 0.f) { cs = FADD(df, rt); sgn2 = 1; }
    else { cs = FSUB(df, rt); sgn2 = -1; }
    float acs = fabsf(cs);
    if (acs > ab) {
        float ct = FDIV(-tb, cs);
        sn1 = FDIV(1.f, sqrtf(FADD(1.f, FMUL(ct, ct))));
        cs1 = FMUL(ct, sn1);
    } else {
        if (ab == 0.f) { cs1 = 1.f; sn1 = 0.f; }
        else {
            float tn = FDIV(-cs, tb);
            cs1 = FDIV(1.f, sqrtf(FADD(1.f, FMUL(tn, tn))));
            sn1 = FMUL(tn, cs1);
        }
    }
    if (sgn1 == sgn2) { float tau = cs1; cs1 = -sn1; sn1 = tau; }
}

// Register-resident index helpers (replace local-memory arrays).
__device__ __forceinline__ float sel3(int i, float v1, float v2, float v3) {
    return i == 1 ? v1 : (i == 2 ? v2 : v3);
}
__device__ __forceinline__ float sel2(int i, float v1, float v2) {
    return i == 1 ? v1 : v2;
}
#define SETD(i, x) do { float _x = (x); if ((i) == 1) d1 = _x; \
                        else if ((i) == 2) d2 = _x; else d3 = _x; } while (0)
#define SETE(i, x) do { float _x = (x); if ((i) == 1) e1 = _x; \
                        else e2 = _x; } while (0)

// Plane rotation on Z columns (1,2): temp=Z[i][2]; Z[i][2]=c*t-s*Z[i][1]; Z[i][1]=s*t+c*Z[i][1]
#define ROT12(c, s) do { float _t; \
    _t = z12; z12 = FSUB(FMUL(c, _t), FMUL(s, z11)); z11 = FADD(FMUL(s, _t), FMUL(c, z11)); \
    _t = z22; z22 = FSUB(FMUL(c, _t), FMUL(s, z21)); z21 = FADD(FMUL(s, _t), FMUL(c, z21)); \
    _t = z32; z32 = FSUB(FMUL(c, _t), FMUL(s, z31)); z31 = FADD(FMUL(s, _t), FMUL(c, z31)); \
} while (0)
#define ROT23(c, s) do { float _t; \
    _t = z13; z13 = FSUB(FMUL(c, _t), FMUL(s, z12)); z12 = FADD(FMUL(s, _t), FMUL(c, z12)); \
    _t = z23; z23 = FSUB(FMUL(c, _t), FMUL(s, z22)); z22 = FADD(FMUL(s, _t), FMUL(c, z22)); \
    _t = z33; z33 = FSUB(FMUL(c, _t), FMUL(s, z32)); z32 = FADD(FMUL(s, _t), FMUL(c, z32)); \
} while (0)
#define SWAPC12() do { float _t; _t = z11; z11 = z12; z12 = _t; \
    _t = z21; z21 = z22; z22 = _t; _t = z31; z31 = z32; z32 = _t; } while (0)
#define SWAPC13() do { float _t; _t = z11; z11 = z13; z13 = _t; \
    _t = z21; z21 = z23; z23 = _t; _t = z31; z31 = z33; z33 = _t; } while (0)
#define SWAPC23() do { float _t; _t = z12; z12 = z13; z13 = _t; \
    _t = z22; z22 = z23; z23 = _t; _t = z32; z32 = z33; z33 = _t; } while (0)

// Covariance accumulation step (frozen sequential order).
__device__ __forceinline__ void cov_acc(float4 q, float px, float py, float pz,
                                        float& a00, float& a10, float& a20,
                                        float& a11, float& a21, float& a22) {
    float dx = FSUB(q.x, px);
    float dy = FSUB(q.y, py);
    float dz = FSUB(q.z, pz);
    a00 = FADD(a00, FMUL(dx, dx));
    a10 = FADD(a10, FMUL(dx, dy));
    a20 = FADD(a20, FMUL(dx, dz));
    a11 = FADD(a11, FMUL(dy, dy));
    a21 = FADD(a21, FMUL(dy, dz));
    a22 = FADD(a22, FMUL(dz, dz));
}

// ---------------------------------------------------------------------------
// Kernel B (fused): thread-per-node covariance -> LAPACK ssyevd replica.
// All solver state in scalars (no runtime-indexed arrays -> no local memory).
// For nn=3 the implicit-shift branch only occurs with (l=1,m2=3) [QL] or
// (l=3,m2=1) [QR], so those loops are specialized with constant indices.
// ---------------------------------------------------------------------------
__global__ void __launch_bounds__(128, 1)
fused_kernel(const int* __restrict__ edge_src,
             const int* __restrict__ num_neighbors,
             float* __restrict__ out, int n, int k) {
    int gi = blockIdx.x * blockDim.x + threadIdx.x;
    if (gi >= n) return;
    float* o = out + (long long)gi * 9;
    if (num_neighbors[gi] <= 1) {
#pragma unroll
        for (int j = 0; j < 9; j++) o[j] = 0.f;
        return;
    }

    // ================= covariance (frozen arithmetic order) ==============
    float4 pc = g_pos4[gi];
    float px = pc.x, py = pc.y, pz = pc.z;
    float a00 = 0.f, a10 = 0.f, a20 = 0.f, a11 = 0.f, a21 = 0.f, a22 = 0.f;
    const int4* es4 = (const int4*)(edge_src + (long long)gi * k);
#pragma unroll 4
    for (int j = 0; j < k / 4; j++) {
        int4 s4 = es4[j];
        float4 q0 = __ldg(&g_pos4[s4.x]);
        float4 q1 = __ldg(&g_pos4[s4.y]);
        float4 q2 = __ldg(&g_pos4[s4.z]);
        float4 q3 = __ldg(&g_pos4[s4.w]);
        cov_acc(q0, px, py, pz, a00, a10, a20, a11, a21, a22);
        cov_acc(q1, px, py, pz, a00, a10, a20, a11, a21, a22);
        cov_acc(q2, px, py, pz, a00, a10, a20, a11, a21, a22);
        cov_acc(q3, px, py, pz, a00, a10, a20, a11, a21, a22);
    }

    // ================= SSYTD2 (lower), n=3 =================
    float d1, d2, d3, e1, e2;
    float tau1 = 0.f, v3 = 0.f;
    {
        float alpha = a10;   // A(2,1)
        float x = a20;       // A(3,1)
        if (x == 0.f) {
            tau1 = 0.f;
            e1 = alpha;
        } else {
            float beta = -copysignf(slapy2f(alpha, x), alpha);
            tau1 = FDIV(FSUB(beta, alpha), beta);
            float rcp = FDIV(1.f, FSUB(alpha, beta));
            v3 = FMUL(x, rcp);
            e1 = beta;
            float w1 = FADD(FMUL(tau1, a11), FMUL(tau1, FMUL(a21, v3)));
            float w2 = FADD(FMUL(tau1, a21), FMUL(FMUL(tau1, v3), a22));
            float dot = FADD(w1, FMUL(w2, v3));
            float al2 = -FMUL(FMUL(0.5f, tau1), dot);
            w1 = FADD(w1, al2);
            w2 = FADD(w2, FMUL(al2, v3));
            a11 = FADD(FADD(a11, -w1), -w1);
            a21 = FADD(FADD(a21, FMUL(v3, -w1)), -w2);
            a22 = FADD(FADD(a22, FMUL(v3, -w2)), FMUL(w2, -v3));
        }
        e2 = a21;
        d1 = a00; d2 = a11; d3 = a22;
    }

    // ================= SSTEQR('I'), n=3, scalarized =================
    const float eps = 5.9604644775390625e-08f;
    const float eps2 = FMUL(eps, eps);
    const float safmin = 1.1754943508222875e-38f;
    const int nmaxit = 90;
    int jtot = 0;

    float z11 = 1.f, z21 = 0.f, z31 = 0.f;
    float z12 = 0.f, z22 = 1.f, z32 = 0.f;
    float z13 = 0.f, z23 = 0.f, z33 = 1.f;
    float wc1, wc2, ws1, ws2;

    int l1 = 1;
    while (l1 <= 3) {
        if (l1 > 1) SETE(l1 - 1, 0.f);
        int m = 3;
        for (int mm = l1; mm <= 2; mm++) {
            float tst = fabsf(sel2(mm, e1, e2));
            if (tst == 0.f) { m = mm; break; }
            if (tst <= FMUL(FMUL(sqrtf(fabsf(sel3(mm, d1, d2, d3))),
                                 sqrtf(fabsf(sel3(mm + 1, d1, d2, d3)))),
                            eps)) {
                SETE(mm, 0.f);
                m = mm; break;
            }
        }
        int l = l1, lsv = l, lend = m, lendsv = lend;
        l1 = m + 1;
        if (lend == l) continue;

        float anorm = 0.f;
        for (int i = l; i <= lend; i++)
            anorm = fmaxf(anorm, fabsf(sel3(i, d1, d2, d3)));
        for (int i = l; i <= lend - 1; i++)
            anorm = fmaxf(anorm, fabsf(sel2(i, e1, e2)));
        if (anorm == 0.f) continue;

        if (fabsf(sel3(lend, d1, d2, d3)) < fabsf(sel3(l, d1, d2, d3))) {
            lend = lsv; l = lendsv;
        }

        if (lend > l) {
            // ---------------- QL iteration ----------------
            while (1) {
                int m2 = lend;
                if (l != lend) {
                    for (int mm = l; mm <= lend - 1; mm++) {
                        float emm = sel2(mm, e1, e2);
                        float tst = FMUL(emm, emm);
                        if (tst <= FADD(FMUL(FMUL(eps2, fabsf(sel3(mm, d1, d2, d3))),
                                             fabsf(sel3(mm + 1, d1, d2, d3))),
                                        safmin)) {
                            m2 = mm; break;
                        }
                    }
                }
                if (m2 < lend) SETE(m2, 0.f);
                float p = sel3(l, d1, d2, d3);
                if (m2 == l) {
                    l = l + 1;
                    if (l <= lend) continue;
                    break;
                }
                if (m2 == l + 1) {
                    float rt1, rt2, c, s;
                    slaev2f(sel3(l, d1, d2, d3), sel2(l, e1, e2),
                            sel3(l + 1, d1, d2, d3), rt1, rt2, c, s);
                    if (l == 1) { ROT12(c, s); } else { ROT23(c, s); }
                    SETD(l, rt1); SETD(l + 1, rt2); SETE(l, 0.f);
                    l = l + 2;
                    if (l <= lend) continue;
                    break;
                }
                if (jtot == nmaxit) break;
                jtot++;
                // shift branch reachable only with l==1, m2==3 (nn=3)
                float g = FDIV(FSUB(d2, p), FMUL(2.f, e1));
                float r = slapy2f(g, 1.f);
                g = FADD(FSUB(d3, p), FDIV(e1, FADD(g, copysignf(r, g))));
                float s = 1.f, c = 1.f;
                p = 0.f;
                {   // i = 2
                    float f = FMUL(s, e2);
                    float b = FMUL(c, e2);
                    slartgf(g, f, c, s, r);
                    g = FSUB(d3, p);
                    r = FADD(FMUL(FSUB(d2, g), s), FMUL(FMUL(2.f, c), b));
                    p = FMUL(s, r);
                    d3 = FADD(g, p);
                    g = FSUB(FMUL(c, r), b);
                    wc2 = c; ws2 = -s;
                }
                {   // i = 1
                    float f = FMUL(s, e1);
                    float b = FMUL(c, e1);
                    slartgf(g, f, c, s, r);
                    e2 = r;
                    g = FSUB(d2, p);
                    r = FADD(FMUL(FSUB(d1, g), s), FMUL(FMUL(2.f, c), b));
                    p = FMUL(s, r);
                    d2 = FADD(g, p);
                    g = FSUB(FMUL(c, r), b);
                    wc1 = c; ws1 = -s;
                }
                // dlasr 'B': j=2 -> cols(2,3); j=1 -> cols(1,2)
                if (wc2 != 1.f || ws2 != 0.f) ROT23(wc2, ws2);
                if (wc1 != 1.f || ws1 != 0.f) ROT12(wc1, ws1);
                d1 = FSUB(d1, p);
                e1 = g;
            }
        } else {
            // ---------------- QR iteration ----------------
            while (1) {
                int m2 = lend;
                if (l != lend) {
                    for (int mm = l; mm >= lend + 1; mm--) {
                        float em = sel2(mm - 1, e1, e2);
                        float tst = FMUL(em, em);
                        if (tst <= FADD(FMUL(FMUL(eps2, fabsf(sel3(mm, d1, d2, d3))),
                                             fabsf(sel3(mm - 1, d1, d2, d3))),
                                        safmin)) {
                            m2 = mm; break;
                        }
                    }
                }
                if (m2 > lend) SETE(m2 - 1, 0.f);
                float p = sel3(l, d1, d2, d3);
                if (m2 == l) {
                    l = l - 1;
                    if (l >= lend) continue;
                    break;
                }
                if (m2 == l - 1) {
                    float rt1, rt2, c, s;
                    slaev2f(sel3(l - 1, d1, d2, d3), sel2(l - 1, e1, e2),
                            sel3(l, d1, d2, d3), rt1, rt2, c, s);
                    if (l == 2) { ROT12(c, s); } else { ROT23(c, s); }
                    SETD(l - 1, rt1); SETD(l, rt2); SETE(l - 1, 0.f);
                    l = l - 2;
                    if (l >= lend) continue;
                    break;
                }
                if (jtot == nmaxit) break;
                jtot++;
                // shift branch reachable only with l==3, m2==1 (nn=3)
                float g = FDIV(FSUB(d2, p), FMUL(2.f, e2));
                float r = slapy2f(g, 1.f);
                g = FADD(FSUB(d1, p), FDIV(e2, FADD(g, copysignf(r, g))));
                float s = 1.f, c = 1.f;
                p = 0.f;
                {   // i = 1
                    float f = FMUL(s, e1);
                    float b = FMUL(c, e1);
                    slartgf(g, f, c, s, r);
                    g = FSUB(d1, p);
                    r = FADD(FMUL(FSUB(d2, g), s), FMUL(FMUL(2.f, c), b));
                    p = FMUL(s, r);
                    d1 = FADD(g, p);
                    g = FSUB(FMUL(c, r), b);
                    wc1 = c; ws1 = s;
                }
                {   // i = 2
                    float f = FMUL(s, e2);
                    float b = FMUL(c, e2);
                    slartgf(g, f, c, s, r);
                    e1 = r;
                    g = FSUB(d2, p);
                    r = FADD(FMUL(FSUB(d3, g), s), FMUL(FMUL(2.f, c), b));
                    p = FMUL(s, r);
                    d2 = FADD(g, p);
                    g = FSUB(FMUL(c, r), b);
                    wc2 = c; ws2 = s;
                }
                // dlasr 'F': j=1 -> cols(1,2); j=2 -> cols(2,3)
                if (wc1 != 1.f || ws1 != 0.f) ROT12(wc1, ws1);
                if (wc2 != 1.f || ws2 != 0.f) ROT23(wc2, ws2);
                d3 = FSUB(d3, p);
                e2 = g;
            }
        }
    }

    // ssteqr final selection sort (ascending, column swaps) — explicit
    {
        // ii = 2 (i = 1)
        int kk = 1; float p = d1;
        if (d2 < p) { kk = 2; p = d2; }
        if (d3 < p) { kk = 3; p = d3; }
        if (kk == 2) { d2 = d1; d1 = p; SWAPC12(); }
        else if (kk == 3) { d3 = d1; d1 = p; SWAPC13(); }
    }
    {
        // ii = 3 (i = 2)
        if (d3 < d2) { float p = d2; d2 = d3; d3 = p; SWAPC23(); }
    }

    // ================= SORMTR ('L','L','N'): Z := H(1)*Z =================
    if (tau1 != 0.f) {
        float w, t;
        w = FADD(z21, FMUL(z31, v3)); t = FMUL(-tau1, w);
        z21 = FADD(z21, t); z31 = FADD(z31, FMUL(v3, t));
        w = FADD(z22, FMUL(z32, v3)); t = FMUL(-tau1, w);
        z22 = FADD(z22, t); z32 = FADD(z32, FMUL(v3, t));
        w = FADD(z23, FMUL(z33, v3)); t = FMUL(-tau1, w);
        z23 = FADD(z23, t); z33 = FADD(z33, FMUL(v3, t));
    }

    // frames[a][b] = vecs[b][a]  =>  out[3a+b] = Z[b+1][a+1]
    o[0] = z11; o[1] = z21; o[2] = z31;
    o[3] = z12; o[4] = z22; o[5] = z32;
    o[6] = z13; o[7] = z23; o[8] = z33;
}

// ---------------------------------------------------------------------------
// Launch
// ---------------------------------------------------------------------------
extern "C" void kernel_launch(void* const* d_in, const int* in_sizes, int n_in,
                              void* d_out, int out_size) {
    const float* pos = (const float*)d_in[0];
    const int* edge_src = (const int*)d_in[1];
    // d_in[2] = edge_dst: unused (edge_dst == repeat(arange(n), k))
    const int* num_neighbors = (const int*)d_in[3];

    int n = in_sizes[3];
    int k = in_sizes[1] / n;

    pad_kernel<<<(n + 255) / 256, 256>>>(pos, n);
    fused_kernel<<<(n + 127) / 128, 128>>>(edge_src, num_neighbors,
                                           (float*)d_out, n, k);
}

// round 9
// speedup vs baseline: 1.4773x; 1.1307x over previous
#include <cuda_runtime.h>
#include <math.h>

#define MAXN 32768

#define FADD __fadd_rn
#define FSUB __fsub_rn
#define FMUL __fmul_rn
#define FDIV __fdiv_rn

// 16B-aligned padded positions: one LDG.128 per neighbor gather.
__device__ float4 g_pos4[MAXN];

// ---------------------------------------------------------------------------
// Kernel A: pad pos[3*i..3*i+2] -> g_pos4[i] (w unused).
// ---------------------------------------------------------------------------
__global__ void pad_kernel(const float* __restrict__ pos, int n) {
    int i = blockIdx.x * blockDim.x + threadIdx.x;
    if (i >= n) return;
    float4 p;
    p.x = pos[3 * i + 0];
    p.y = pos[3 * i + 1];
    p.z = pos[3 * i + 2];
    p.w = 0.f;
    g_pos4[i] = p;
}

// ---------------------------------------------------------------------------
// LAPACK fp32 helpers, netlib-expression-faithful (LAPACK >= 3.10).
// FROZEN: arithmetic validated at rel_err 3.4e-7 — do not reorder.
// ---------------------------------------------------------------------------
__device__ __forceinline__ float slapy2f(float x, float y) {
    float xa = fabsf(x), ya = fabsf(y);
    float w = fmaxf(xa, ya), z = fminf(xa, ya);
    if (z == 0.f) return w;
    float t = FDIV(z, w);
    return FMUL(w, sqrtf(FADD(1.f, FMUL(t, t))));
}

__device__ __forceinline__ void slartgf(float f, float g, float& c, float& s,
                                        float& r) {
    if (g == 0.f) {
        c = 1.f; s = 0.f; r = f;
    } else if (f == 0.f) {
        c = 0.f; s = copysignf(1.f, g); r = fabsf(g);
    } else {
        float d = sqrtf(FADD(FMUL(f, f), FMUL(g, g)));
        float p = FDIV(1.f, d);
        c = FMUL(fabsf(f), p);
        s = FMUL(g, copysignf(p, f));
        r = copysignf(d, f);
    }
}

__device__ void slaev2f(float a, float b, float c0, float& rt1, float& rt2,
                        float& cs1, float& sn1) {
    float sm = FADD(a, c0);
    float df = FSUB(a, c0);
    float adf = fabsf(df);
    float tb = FADD(b, b);
    float ab = fabsf(tb);
    float acmx, acmn;
    if (fabsf(a) > fabsf(c0)) { acmx = a; acmn = c0; }
    else { acmx = c0; acmn = a; }
    float rt;
    if (adf > ab) {
        float t = FDIV(ab, adf);
        rt = FMUL(adf, sqrtf(FADD(1.f, FMUL(t, t))));
    } else if (adf < ab) {
        float t = FDIV(adf, ab);
        rt = FMUL(ab, sqrtf(FADD(1.f, FMUL(t, t))));
    } else {
        rt = FMUL(ab, sqrtf(2.f));
    }
    int sgn1;
    if (sm < 0.f) {
        rt1 = FMUL(0.5f, FSUB(sm, rt)); sgn1 = -1;
        rt2 = FSUB(FMUL(FDIV(acmx, rt1), acmn), FMUL(FDIV(b, rt1), b));
    } else if (sm > 0.f) {
        rt1 = FMUL(0.5f, FADD(sm, rt)); sgn1 = 1;
        rt2 = FSUB(FMUL(FDIV(acmx, rt1), acmn), FMUL(FDIV(b, rt1), b));
    } else {
        rt1 = FMUL(0.5f, rt); rt2 = FMUL(-0.5f, rt); sgn1 = 1;
    }
    int sgn2;
    float cs;
    if (df >= 0.f) { cs = FADD(df, rt); sgn2 = 1; }
    else { cs = FSUB(df, rt); sgn2 = -1; }
    float acs = fabsf(cs);
    if (acs > ab) {
        float ct = FDIV(-tb, cs);
        sn1 = FDIV(1.f, sqrtf(FADD(1.f, FMUL(ct, ct))));
        cs1 = FMUL(ct, sn1);
    } else {
        if (ab == 0.f) { cs1 = 1.f; sn1 = 0.f; }
        else {
            float tn = FDIV(-cs, tb);
            cs1 = FDIV(1.f, sqrtf(FADD(1.f, FMUL(tn, tn))));
            sn1 = FMUL(tn, cs1);
        }
    }
    if (sgn1 == sgn2) { float tau = cs1; cs1 = -sn1; sn1 = tau; }
}

// Register-resident index helpers (no local memory).
__device__ __forceinline__ float sel3(int i, float v1, float v2, float v3) {
    return i == 1 ? v1 : (i == 2 ? v2 : v3);
}
__device__ __forceinline__ float sel2(int i, float v1, float v2) {
    return i == 1 ? v1 : v2;
}
#define SETD(i, x) do { float _x = (x); if ((i) == 1) d1 = _x; \
                        else if ((i) == 2) d2 = _x; else d3 = _x; } while (0)
#define SETE(i, x) do { float _x = (x); if ((i) == 1) e1 = _x; \
                        else e2 = _x; } while (0)

// Standard rotations: hi = higher column index.
#define ROT12(c, s) do { float _t; \
    _t = z12; z12 = FSUB(FMUL(c, _t), FMUL(s, z11)); z11 = FADD(FMUL(s, _t), FMUL(c, z11)); \
    _t = z22; z22 = FSUB(FMUL(c, _t), FMUL(s, z21)); z21 = FADD(FMUL(s, _t), FMUL(c, z21)); \
    _t = z32; z32 = FSUB(FMUL(c, _t), FMUL(s, z31)); z31 = FADD(FMUL(s, _t), FMUL(c, z31)); \
} while (0)
#define ROT23(c, s) do { float _t; \
    _t = z13; z13 = FSUB(FMUL(c, _t), FMUL(s, z12)); z12 = FADD(FMUL(s, _t), FMUL(c, z12)); \
    _t = z23; z23 = FSUB(FMUL(c, _t), FMUL(s, z22)); z22 = FADD(FMUL(s, _t), FMUL(c, z22)); \
    _t = z33; z33 = FSUB(FMUL(c, _t), FMUL(s, z32)); z32 = FADD(FMUL(s, _t), FMUL(c, z32)); \
} while (0)
// Mirrored rotations (QR direction; s already negated vs QR's own s — the
// combination is bitwise-identical to the original QR rotations).
// MROTA: virtual cols (2,3) = real (2,1), hi = real col 1.
#define MROTA(c, s) do { float _t; \
    _t = z11; z11 = FSUB(FMUL(c, _t), FMUL(s, z12)); z12 = FADD(FMUL(s, _t), FMUL(c, z12)); \
    _t = z21; z21 = FSUB(FMUL(c, _t), FMUL(s, z22)); z22 = FADD(FMUL(s, _t), FMUL(c, z22)); \
    _t = z31; z31 = FSUB(FMUL(c, _t), FMUL(s, z32)); z32 = FADD(FMUL(s, _t), FMUL(c, z32)); \
} while (0)
// MROTB: virtual cols (1,2) = real (3,2), hi = real col 2.
#define MROTB(c, s) do { float _t; \
    _t = z12; z12 = FSUB(FMUL(c, _t), FMUL(s, z13)); z13 = FADD(FMUL(s, _t), FMUL(c, z13)); \
    _t = z22; z22 = FSUB(FMUL(c, _t), FMUL(s, z23)); z23 = FADD(FMUL(s, _t), FMUL(c, z23)); \
    _t = z32; z32 = FSUB(FMUL(c, _t), FMUL(s, z33)); z33 = FADD(FMUL(s, _t), FMUL(c, z33)); \
} while (0)
#define SWAPC12() do { float _t; _t = z11; z11 = z12; z12 = _t; \
    _t = z21; z21 = z22; z22 = _t; _t = z31; z31 = z32; z32 = _t; } while (0)
#define SWAPC13() do { float _t; _t = z11; z11 = z13; z13 = _t; \
    _t = z21; z21 = z23; z23 = _t; _t = z31; z31 = z33; z33 = _t; } while (0)
#define SWAPC23() do { float _t; _t = z12; z12 = z13; z13 = _t; \
    _t = z22; z22 = z23; z23 = _t; _t = z32; z32 = z33; z33 = _t; } while (0)

// Covariance accumulation step (frozen sequential order).
__device__ __forceinline__ void cov_acc(float4 q, float px, float py, float pz,
                                        float& a00, float& a10, float& a20,
                                        float& a11, float& a21, float& a22) {
    float dx = FSUB(q.x, px);
    float dy = FSUB(q.y, py);
    float dz = FSUB(q.z, pz);
    a00 = FADD(a00, FMUL(dx, dx));
    a10 = FADD(a10, FMUL(dx, dy));
    a20 = FADD(a20, FMUL(dx, dz));
    a11 = FADD(a11, FMUL(dy, dy));
    a21 = FADD(a21, FMUL(dy, dz));
    a22 = FADD(a22, FMUL(dz, dz));
}

// ---------------------------------------------------------------------------
// Kernel B (fused): thread-per-node covariance -> LAPACK ssyevd replica.
// QL and QR iterations unified into ONE loop via exact index mirroring
// (bitwise-identical arithmetic; kills warp divergence between directions).
// ---------------------------------------------------------------------------
__global__ void __launch_bounds__(128, 1)
fused_kernel(const int* __restrict__ edge_src,
             const int* __restrict__ num_neighbors,
             float* __restrict__ out, int n, int k) {
    int gi = blockIdx.x * blockDim.x + threadIdx.x;
    if (gi >= n) return;
    float* o = out + (long long)gi * 9;
    if (num_neighbors[gi] <= 1) {
#pragma unroll
        for (int j = 0; j < 9; j++) o[j] = 0.f;
        return;
    }

    // ================= covariance (frozen arithmetic order) ==============
    float4 pc = g_pos4[gi];
    float px = pc.x, py = pc.y, pz = pc.z;
    float a00 = 0.f, a10 = 0.f, a20 = 0.f, a11 = 0.f, a21 = 0.f, a22 = 0.f;
    const int4* es4 = (const int4*)(edge_src + (long long)gi * k);
#pragma unroll 8
    for (int j = 0; j < k / 4; j++) {
        int4 s4 = es4[j];
        float4 q0 = __ldg(&g_pos4[s4.x]);
        float4 q1 = __ldg(&g_pos4[s4.y]);
        float4 q2 = __ldg(&g_pos4[s4.z]);
        float4 q3 = __ldg(&g_pos4[s4.w]);
        cov_acc(q0, px, py, pz, a00, a10, a20, a11, a21, a22);
        cov_acc(q1, px, py, pz, a00, a10, a20, a11, a21, a22);
        cov_acc(q2, px, py, pz, a00, a10, a20, a11, a21, a22);
        cov_acc(q3, px, py, pz, a00, a10, a20, a11, a21, a22);
    }

    // ================= SSYTD2 (lower), n=3 =================
    float d1, d2, d3, e1, e2;
    float tau1 = 0.f, v3 = 0.f;
    {
        float alpha = a10;   // A(2,1)
        float x = a20;       // A(3,1)
        if (x == 0.f) {
            tau1 = 0.f;
            e1 = alpha;
        } else {
            float beta = -copysignf(slapy2f(alpha, x), alpha);
            tau1 = FDIV(FSUB(beta, alpha), beta);
            float rcp = FDIV(1.f, FSUB(alpha, beta));
            v3 = FMUL(x, rcp);
            e1 = beta;
            float w1 = FADD(FMUL(tau1, a11), FMUL(tau1, FMUL(a21, v3)));
            float w2 = FADD(FMUL(tau1, a21), FMUL(FMUL(tau1, v3), a22));
            float dot = FADD(w1, FMUL(w2, v3));
            float al2 = -FMUL(FMUL(0.5f, tau1), dot);
            w1 = FADD(w1, al2);
            w2 = FADD(w2, FMUL(al2, v3));
            a11 = FADD(FADD(a11, -w1), -w1);
            a21 = FADD(FADD(a21, FMUL(v3, -w1)), -w2);
            a22 = FADD(FADD(a22, FMUL(v3, -w2)), FMUL(w2, -v3));
        }
        e2 = a21;
        d1 = a00; d2 = a11; d3 = a22;
    }

    // ================= SSTEQR('I'), n=3, scalarized + direction-unified ====
    const float eps = 5.9604644775390625e-08f;
    const float eps2 = FMUL(eps, eps);
    const float safmin = 1.1754943508222875e-38f;
    const int nmaxit = 90;
    int jtot = 0;

    float z11 = 1.f, z21 = 0.f, z31 = 0.f;
    float z12 = 0.f, z22 = 1.f, z32 = 0.f;
    float z13 = 0.f, z23 = 0.f, z33 = 1.f;

    int l1 = 1;
    while (l1 <= 3) {
        if (l1 > 1) SETE(l1 - 1, 0.f);
        int m = 3;
        for (int mm = l1; mm <= 2; mm++) {
            float tst = fabsf(sel2(mm, e1, e2));
            if (tst == 0.f) { m = mm; break; }
            if (tst <= FMUL(FMUL(sqrtf(fabsf(sel3(mm, d1, d2, d3))),
                                 sqrtf(fabsf(sel3(mm + 1, d1, d2, d3)))),
                            eps)) {
                SETE(mm, 0.f);
                m = mm; break;
            }
        }
        int l = l1, lsv = l, lend = m, lendsv = lend;
        l1 = m + 1;
        if (lend == l) continue;

        float anorm = 0.f;
        for (int i = l; i <= lend; i++)
            anorm = fmaxf(anorm, fabsf(sel3(i, d1, d2, d3)));
        for (int i = l; i <= lend - 1; i++)
            anorm = fmaxf(anorm, fabsf(sel2(i, e1, e2)));
        if (anorm == 0.f) continue;

        if (fabsf(sel3(lend, d1, d2, d3)) < fabsf(sel3(l, d1, d2, d3))) {
            lend = lsv; l = lendsv;
        }

        // Unified iteration: QL runs on real indices; QR runs as QL on the
        // mirror vd[i]=d[4-i], ve[i]=e[3-i] (verified bitwise-exact).
        bool ql = (lend > l);
        int lv = ql ? l : 4 - l;
        int lendv = ql ? lend : 4 - lend;

        while (1) {
            // find small subdiagonal (virtual ascending == real QR descending)
            int m2 = lendv;
            if (lv != lendv) {
                for (int mm = lv; mm <= lendv - 1; mm++) {
                    float emm = sel2(ql ? mm : 3 - mm, e1, e2);
                    float tst = FMUL(emm, emm);
                    float dmm = sel3(ql ? mm : 4 - mm, d1, d2, d3);
                    float dmm1 = sel3(ql ? mm + 1 : 3 - mm, d1, d2, d3);
                    if (tst <= FADD(FMUL(FMUL(eps2, fabsf(dmm)), fabsf(dmm1)),
                                    safmin)) {
                        m2 = mm; break;
                    }
                }
            }
            if (m2 < lendv) SETE(ql ? m2 : 3 - m2, 0.f);
            float p = sel3(ql ? lv : 4 - lv, d1, d2, d3);
            if (m2 == lv) {
                lv = lv + 1;
                if (lv <= lendv) continue;
                break;
            }
            if (m2 == lv + 1) {
                // 2x2 block: slaev2 args swap under mirror (direction-specific)
                float rt1, rt2, c, s;
                float bb = sel2(ql ? lv : 3 - lv, e1, e2);
                float aa, cc;
                if (ql) {
                    aa = sel3(lv, d1, d2, d3);
                    cc = sel3(lv + 1, d1, d2, d3);
                } else {
                    aa = sel3(3 - lv, d1, d2, d3);
                    cc = sel3(4 - lv, d1, d2, d3);
                }
                slaev2f(aa, bb, cc, rt1, rt2, c, s);
                // real rotation pair: ql ? (lv,lv+1) : (3-lv,4-lv); hi = larger
                if ((ql && lv == 1) || (!ql && lv == 2)) { ROT12(c, s); }
                else { ROT23(c, s); }
                if (ql) {
                    SETD(lv, rt1); SETD(lv + 1, rt2); SETE(lv, 0.f);
                } else {
                    SETD(3 - lv, rt1); SETD(4 - lv, rt2); SETE(3 - lv, 0.f);
                }
                lv = lv + 2;
                if (lv <= lendv) continue;
                break;
            }
            if (jtot == nmaxit) break;
            jtot++;
            // shift branch: only (lv=1, m2=3, lendv=3) reachable for nn=3
            float vd1 = ql ? d1 : d3, vd3 = ql ? d3 : d1;
            float ve1 = ql ? e1 : e2, ve2 = ql ? e2 : e1;
            float g = FDIV(FSUB(d2, p), FMUL(2.f, ve1));
            float r = slapy2f(g, 1.f);
            g = FADD(FSUB(vd3, p), FDIV(ve1, FADD(g, copysignf(r, g))));
            float s = 1.f, c = 1.f;
            p = 0.f;
            float wc1, wc2, ws1, ws2;
            {   // virtual i = 2
                float f = FMUL(s, ve2);
                float b = FMUL(c, ve2);
                slartgf(g, f, c, s, r);
                g = FSUB(vd3, p);
                r = FADD(FMUL(FSUB(d2, g), s), FMUL(FMUL(2.f, c), b));
                p = FMUL(s, r);
                vd3 = FADD(g, p);
                g = FSUB(FMUL(c, r), b);
                wc2 = c; ws2 = -s;
            }
            {   // virtual i = 1
                float f = FMUL(s, ve1);
                float b = FMUL(c, ve1);
                slartgf(g, f, c, s, r);
                ve2 = r;
                g = FSUB(d2, p);
                r = FADD(FMUL(FSUB(vd1, g), s), FMUL(FMUL(2.f, c), b));
                p = FMUL(s, r);
                d2 = FADD(g, p);
                g = FSUB(FMUL(c, r), b);
                wc1 = c; ws1 = -s;
            }
            // dlasr 'B' in virtual cols == 'F' in real cols for the mirror
            if (wc2 != 1.f || ws2 != 0.f) {
                if (ql) { ROT23(wc2, ws2); } else { MROTA(wc2, ws2); }
            }
            if (wc1 != 1.f || ws1 != 0.f) {
                if (ql) { ROT12(wc1, ws1); } else { MROTB(wc1, ws1); }
            }
            vd1 = FSUB(vd1, p);
            ve1 = g;
            if (ql) { d1 = vd1; d3 = vd3; e1 = ve1; e2 = ve2; }
            else    { d3 = vd1; d1 = vd3; e2 = ve1; e1 = ve2; }
        }
    }

    // ssteqr final selection sort (ascending, column swaps) — explicit
    {
        int kk = 1; float p = d1;
        if (d2 < p) { kk = 2; p = d2; }
        if (d3 < p) { kk = 3; p = d3; }
        if (kk == 2) { d2 = d1; d1 = p; SWAPC12(); }
        else if (kk == 3) { d3 = d1; d1 = p; SWAPC13(); }
    }
    {
        if (d3 < d2) { float p = d2; d2 = d3; d3 = p; SWAPC23(); }
    }

    // ================= SORMTR ('L','L','N'): Z := H(1)*Z =================
    if (tau1 != 0.f) {
        float w, t;
        w = FADD(z21, FMUL(z31, v3)); t = FMUL(-tau1, w);
        z21 = FADD(z21, t); z31 = FADD(z31, FMUL(v3, t));
        w = FADD(z22, FMUL(z32, v3)); t = FMUL(-tau1, w);
        z22 = FADD(z22, t); z32 = FADD(z32, FMUL(v3, t));
        w = FADD(z23, FMUL(z33, v3)); t = FMUL(-tau1, w);
        z23 = FADD(z23, t); z33 = FADD(z33, FMUL(v3, t));
    }

    // frames[a][b] = vecs[b][a]  =>  out[3a+b] = Z[b+1][a+1]
    o[0] = z11; o[1] = z21; o[2] = z31;
    o[3] = z12; o[4] = z22; o[5] = z32;
    o[6] = z13; o[7] = z23; o[8] = z33;
}

// ---------------------------------------------------------------------------
// Launch
// ---------------------------------------------------------------------------
extern "C" void kernel_launch(void* const* d_in, const int* in_sizes, int n_in,
                              void* d_out, int out_size) {
    const float* pos = (const float*)d_in[0];
    const int* edge_src = (const int*)d_in[1];
    // d_in[2] = edge_dst: unused (edge_dst == repeat(arange(n), k))
    const int* num_neighbors = (const int*)d_in[3];

    int n = in_sizes[3];
    int k = in_sizes[1] / n;

    pad_kernel<<<(n + 255) / 256, 256>>>(pos, n);
    fused_kernel<<<(n + 127) / 128, 128>>>(edge_src, num_neighbors,
                                           (float*)d_out, n, k);
}